// round 1
// baseline (speedup 1.0000x reference)
#include <cuda_runtime.h>

#define SQ   1024   // spatial sequence length (16*64)
#define CH   64     // channels == heads (c = 1 per head)
#define BB   2      // batch
#define NHB  128    // b*g head-batches

// Scratch (allocation-free rule: __device__ globals)
__device__ float g_q[NHB * SQ];
__device__ float g_k[NHB * SQ];
__device__ float g_v[NHB * SQ];
__device__ float g_o[NHB * SQ];

__device__ __forceinline__ float ex2f(float x) {
    float r;
    asm("ex2.approx.ftz.f32 %0, %1;" : "=f"(r) : "f"(x));
    return r;
}

// ---------------------------------------------------------------------------
// Channel-mixing 1x1 conv: Y[b,o,s] = bias[o] + sum_c W[o,c] * X[b,c,s] (+res)
// grid: (SQ/16, BB), block: 256 threads.
// Thread (o = tid&63, sq = tid>>6) computes a float4 of s for one o.
// ---------------------------------------------------------------------------
template <bool RES>
__global__ void proj_kernel(const float* __restrict__ Xext, int xsel,
                            const float* __restrict__ W,
                            const float* __restrict__ bias,
                            const float* __restrict__ res,
                            float* __restrict__ Yext, int ysel)
{
    __shared__ float Wsh[CH][CH + 1];   // +1 pad -> conflict-free column reads
    __shared__ float bsh[CH];

    const float* X = xsel ? g_o : Xext;
    float* Y = (ysel == 0) ? g_q : (ysel == 1) ? g_k : (ysel == 2) ? g_v : Yext;

    int tid = threadIdx.x;
    for (int i = tid; i < CH * CH; i += 256)
        Wsh[i >> 6][i & 63] = W[i];
    if (tid < CH) bsh[tid] = bias[tid];
    __syncthreads();

    int b  = blockIdx.y;
    int o  = tid & 63;
    int sq = tid >> 6;                       // 0..3
    int s  = blockIdx.x * 16 + sq * 4;       // float4-aligned

    float bv = bsh[o];
    float ax = bv, ay = bv, az = bv, aw = bv;

    const float* xbase = X + b * CH * SQ + s;
#pragma unroll
    for (int c = 0; c < CH; c++) {
        float  w  = Wsh[o][c];
        float4 xv = *reinterpret_cast<const float4*>(xbase + c * SQ);
        ax = fmaf(w, xv.x, ax);
        ay = fmaf(w, xv.y, ay);
        az = fmaf(w, xv.z, az);
        aw = fmaf(w, xv.w, aw);
    }

    float* yb = Y + (b * CH + o) * SQ + s;
    if (RES) {
        const float4 rv = *reinterpret_cast<const float4*>(res + (b * CH + o) * SQ + s);
        ax += rv.x; ay += rv.y; az += rv.z; aw += rv.w;
    }
    float4 out;
    out.x = ax; out.y = ay; out.z = az; out.w = aw;
    *reinterpret_cast<float4*>(yb) = out;
}

// ---------------------------------------------------------------------------
// Rank-1 attention per head (c = 1):
//   o_s = sum_t exp2(q_s * k_t * log2e/8) * v_t / sum_t exp2(q_s * k_t * log2e/8)
// grid: 1024 = 128 heads * 8 s-chunks; block: 128 threads (one s per thread).
// k,v staged in smem; inner loop is uniform-address broadcast LDS.128.
// ---------------------------------------------------------------------------
__global__ void attn_kernel()
{
    __shared__ float sk[SQ];
    __shared__ float sv[SQ];

    int hb    = blockIdx.x >> 3;
    int chunk = blockIdx.x & 7;
    int tid   = threadIdx.x;

    const float KS = 0.18033688011112042f;   // log2(e) / sqrt(64)
    const float* kp = g_k + hb * SQ;
    const float* vp = g_v + hb * SQ;
    for (int i = tid; i < SQ; i += 128) {
        sk[i] = kp[i] * KS;
        sv[i] = vp[i];
    }
    __syncthreads();

    int   s = chunk * 128 + tid;
    float q = g_q[hb * SQ + s];

    const float4* k4 = reinterpret_cast<const float4*>(sk);
    const float4* v4 = reinterpret_cast<const float4*>(sv);

    float Z0 = 0.f, Z1 = 0.f, Z2 = 0.f, Z3 = 0.f;
    float N0 = 0.f, N1 = 0.f, N2 = 0.f, N3 = 0.f;

#pragma unroll 4
    for (int it = 0; it < SQ / 4; it++) {
        float4 kk = k4[it];
        float4 vv = v4[it];
        float e0 = ex2f(q * kk.x);
        float e1 = ex2f(q * kk.y);
        float e2 = ex2f(q * kk.z);
        float e3 = ex2f(q * kk.w);
        Z0 += e0; Z1 += e1; Z2 += e2; Z3 += e3;
        N0 = fmaf(e0, vv.x, N0);
        N1 = fmaf(e1, vv.y, N1);
        N2 = fmaf(e2, vv.z, N2);
        N3 = fmaf(e3, vv.w, N3);
    }

    float Z = (Z0 + Z1) + (Z2 + Z3);
    float N = (N0 + N1) + (N2 + N3);
    g_o[hb * SQ + s] = N / Z;
}

extern "C" void kernel_launch(void* const* d_in, const int* in_sizes, int n_in,
                              void* d_out, int out_size)
{
    const float* x  = (const float*)d_in[0];
    const float* Wq = (const float*)d_in[1];
    const float* bq = (const float*)d_in[2];
    const float* Wk = (const float*)d_in[3];
    const float* bk = (const float*)d_in[4];
    const float* Wv = (const float*)d_in[5];
    const float* bv = (const float*)d_in[6];
    const float* Wo = (const float*)d_in[7];
    const float* bo = (const float*)d_in[8];
    float* out = (float*)d_out;

    dim3 pgrid(SQ / 16, BB);

    // q, k, v projections
    proj_kernel<false><<<pgrid, 256>>>(x, 0, Wq, bq, nullptr, nullptr, 0);
    proj_kernel<false><<<pgrid, 256>>>(x, 0, Wk, bk, nullptr, nullptr, 1);
    proj_kernel<false><<<pgrid, 256>>>(x, 0, Wv, bv, nullptr, nullptr, 2);

    // rank-1 attention per head
    attn_kernel<<<NHB * 8, 128>>>();

    // output projection + residual
    proj_kernel<true><<<pgrid, 256>>>(nullptr, 1, Wo, bo, x, out, 3);
}

// round 2
// speedup vs baseline: 4.6757x; 4.6757x over previous
#include <cuda_runtime.h>

#define SQ   1024   // spatial sequence length (16*64)
#define CH   64     // channels == heads (c = 1 per head)
#define BB   2      // batch
#define NHB  128    // b*g head-batches
#define M    16     // Chebyshev nodes / polynomial terms

// Scratch (allocation-free rule: __device__ global)
__device__ float g_o[NHB * SQ];

__device__ __forceinline__ float ex2f(float x) {
    float r;
    asm("ex2.approx.ftz.f32 %0, %1;" : "=f"(r) : "f"(x));
    return r;
}

// ---------------------------------------------------------------------------
// K1: fused per-head QKV projection + rank-1 attention via Chebyshev proxy.
// One block per (batch, head). 256 threads.
//   Phase 1: q,k,v rows of the 1x1-conv GEMM (coalesced float4 x reads).
//   Phase 2: block min/max of q -> interval [c-r, c+r].
//   Phase 3: evaluate f(a)=sum exp2(a*kh_t), g(a)=sum v_t*exp2(a*kh_t)
//            at 16 Chebyshev nodes (2 nodes per warp, warp reductions).
//   Phase 4: DCT -> Chebyshev coefficients.
//   Phase 5: Clenshaw per s, o_s = g(q_s)/f(q_s).
// ---------------------------------------------------------------------------
__global__ __launch_bounds__(256) void fused_qkv_attn(
    const float* __restrict__ x,
    const float* __restrict__ Wq, const float* __restrict__ bq,
    const float* __restrict__ Wk, const float* __restrict__ bk,
    const float* __restrict__ Wv, const float* __restrict__ bv)
{
    __shared__ float wq[CH], wk[CH], wv[CH];
    __shared__ float sqv[SQ], skh[SQ], svv[SQ];
    __shared__ float fj[M], gj[M], ca[M], cb[M];
    __shared__ float rmin[8], rmax[8];
    __shared__ float sc[3];   // center, radius, 1/radius

    const int tid = threadIdx.x;
    const int hb  = blockIdx.x;
    const int b   = hb >> 6;
    const int h   = hb & 63;

    if (tid < CH)            wq[tid]          = Wq[h * CH + tid];
    else if (tid < 2 * CH)   wk[tid - CH]     = Wk[h * CH + (tid - CH)];
    else if (tid < 3 * CH)   wv[tid - 2 * CH] = Wv[h * CH + (tid - 2 * CH)];
    const float bqh = bq[h], bkh = bk[h], bvh = bv[h];
    __syncthreads();

    const float KS = 0.18033688011112042f;   // log2(e) / sqrt(64)
    const int s0 = tid * 4;

    // Phase 1: projections (each thread: 4 consecutive s, coalesced loads)
    float4 aq = {bqh, bqh, bqh, bqh};
    float4 ak = {bkh, bkh, bkh, bkh};
    float4 av = {bvh, bvh, bvh, bvh};
    const float* xb = x + (size_t)b * CH * SQ + s0;
#pragma unroll
    for (int c = 0; c < CH; c++) {
        float4 xv = *reinterpret_cast<const float4*>(xb + c * SQ);
        float wqc = wq[c], wkc = wk[c], wvc = wv[c];
        aq.x = fmaf(wqc, xv.x, aq.x); aq.y = fmaf(wqc, xv.y, aq.y);
        aq.z = fmaf(wqc, xv.z, aq.z); aq.w = fmaf(wqc, xv.w, aq.w);
        ak.x = fmaf(wkc, xv.x, ak.x); ak.y = fmaf(wkc, xv.y, ak.y);
        ak.z = fmaf(wkc, xv.z, ak.z); ak.w = fmaf(wkc, xv.w, ak.w);
        av.x = fmaf(wvc, xv.x, av.x); av.y = fmaf(wvc, xv.y, av.y);
        av.z = fmaf(wvc, xv.z, av.z); av.w = fmaf(wvc, xv.w, av.w);
    }
    *reinterpret_cast<float4*>(sqv + s0) = aq;
    float4 akk; akk.x = ak.x * KS; akk.y = ak.y * KS; akk.z = ak.z * KS; akk.w = ak.w * KS;
    *reinterpret_cast<float4*>(skh + s0) = akk;
    *reinterpret_cast<float4*>(svv + s0) = av;

    // Phase 2: q min/max
    float qmn = fminf(fminf(aq.x, aq.y), fminf(aq.z, aq.w));
    float qmx = fmaxf(fmaxf(aq.x, aq.y), fmaxf(aq.z, aq.w));
#pragma unroll
    for (int d = 16; d; d >>= 1) {
        qmn = fminf(qmn, __shfl_xor_sync(0xffffffffu, qmn, d));
        qmx = fmaxf(qmx, __shfl_xor_sync(0xffffffffu, qmx, d));
    }
    const int w = tid >> 5, l = tid & 31;
    if (l == 0) { rmin[w] = qmn; rmax[w] = qmx; }
    __syncthreads();
    if (tid == 0) {
        float mn = rmin[0], mx = rmax[0];
#pragma unroll
        for (int i = 1; i < 8; i++) { mn = fminf(mn, rmin[i]); mx = fmaxf(mx, rmax[i]); }
        float cc = 0.5f * (mn + mx);
        float rr = fmaxf(0.5f * (mx - mn), 1e-4f);
        sc[0] = cc; sc[1] = rr; sc[2] = 1.0f / rr;
    }
    __syncthreads();
    const float cc = sc[0], rr = sc[1], invr = sc[2];

    // Phase 3: node evaluation — warp w handles nodes 2w and 2w+1
    {
        const float PI_M = 3.14159265358979f / (float)M;
        const int j0 = 2 * w, j1 = 2 * w + 1;
        const float x0 = cc + rr * cosf(((float)j0 + 0.5f) * PI_M);
        const float x1 = cc + rr * cosf(((float)j1 + 0.5f) * PI_M);
        float f0 = 0.f, f1 = 0.f, g0 = 0.f, g1 = 0.f;
#pragma unroll 8
        for (int t = l; t < SQ; t += 32) {
            float kv = skh[t], vv = svv[t];
            float e0 = ex2f(x0 * kv);
            float e1 = ex2f(x1 * kv);
            f0 += e0; f1 += e1;
            g0 = fmaf(e0, vv, g0);
            g1 = fmaf(e1, vv, g1);
        }
#pragma unroll
        for (int d = 16; d; d >>= 1) {
            f0 += __shfl_xor_sync(0xffffffffu, f0, d);
            f1 += __shfl_xor_sync(0xffffffffu, f1, d);
            g0 += __shfl_xor_sync(0xffffffffu, g0, d);
            g1 += __shfl_xor_sync(0xffffffffu, g1, d);
        }
        if (l == 0) { fj[j0] = f0; fj[j1] = f1; gj[j0] = g0; gj[j1] = g1; }
    }
    __syncthreads();

    // Phase 4: DCT -> Chebyshev coefficients (threads 0..15)
    if (tid < M) {
        const float PI_M = 3.14159265358979f / (float)M;
        float af = 0.f, ag = 0.f;
#pragma unroll
        for (int j = 0; j < M; j++) {
            float wgt = cosf((float)tid * ((float)j + 0.5f) * PI_M);
            af = fmaf(fj[j], wgt, af);
            ag = fmaf(gj[j], wgt, ag);
        }
        float scale = (tid == 0) ? (1.0f / M) : (2.0f / M);
        ca[tid] = af * scale;
        cb[tid] = ag * scale;
    }
    __syncthreads();

    // Phase 5: Clenshaw evaluation, o_s = g(q_s)/f(q_s)
    float4 q4 = *reinterpret_cast<float4*>(sqv + s0);
    float qs[4] = {q4.x, q4.y, q4.z, q4.w};
    float os[4];
#pragma unroll
    for (int i = 0; i < 4; i++) {
        float u  = (qs[i] - cc) * invr;
        float u2 = 2.f * u;
        float b1 = 0.f, b2 = 0.f, d1 = 0.f, d2 = 0.f;
#pragma unroll
        for (int k = M - 1; k >= 1; k--) {
            float tb = fmaf(u2, b1, ca[k] - b2); b2 = b1; b1 = tb;
            float td = fmaf(u2, d1, cb[k] - d2); d2 = d1; d1 = td;
        }
        float f = fmaf(u, b1, ca[0] - b2);
        float g = fmaf(u, d1, cb[0] - d2);
        os[i] = __fdividef(g, f);
    }
    float4 out; out.x = os[0]; out.y = os[1]; out.z = os[2]; out.w = os[3];
    *reinterpret_cast<float4*>(g_o + hb * SQ + s0) = out;
}

// ---------------------------------------------------------------------------
// K2: output projection + residual. One block per (batch, out-channel).
// Fully coalesced float4 loads/stores.
// ---------------------------------------------------------------------------
__global__ __launch_bounds__(256) void out_proj(
    const float* __restrict__ x,
    const float* __restrict__ Wo, const float* __restrict__ bo,
    float* __restrict__ out)
{
    __shared__ float wsh[CH];
    const int tid = threadIdx.x;
    const int bo_ = blockIdx.x;
    const int b = bo_ >> 6;
    const int o = bo_ & 63;

    if (tid < CH) wsh[tid] = Wo[o * CH + tid];
    const float bias = bo[o];
    __syncthreads();

    const int s0 = tid * 4;
    float4 acc = {bias, bias, bias, bias};
    const float* ob = g_o + b * CH * SQ + s0;
#pragma unroll
    for (int c = 0; c < CH; c++) {
        float4 ov = *reinterpret_cast<const float4*>(ob + c * SQ);
        float wc = wsh[c];
        acc.x = fmaf(wc, ov.x, acc.x);
        acc.y = fmaf(wc, ov.y, acc.y);
        acc.z = fmaf(wc, ov.z, acc.z);
        acc.w = fmaf(wc, ov.w, acc.w);
    }
    const float4 rv = *reinterpret_cast<const float4*>(x + (b * CH + o) * SQ + s0);
    acc.x += rv.x; acc.y += rv.y; acc.z += rv.z; acc.w += rv.w;
    *reinterpret_cast<float4*>(out + (b * CH + o) * SQ + s0) = acc;
}

extern "C" void kernel_launch(void* const* d_in, const int* in_sizes, int n_in,
                              void* d_out, int out_size)
{
    const float* x  = (const float*)d_in[0];
    const float* Wq = (const float*)d_in[1];
    const float* bq = (const float*)d_in[2];
    const float* Wk = (const float*)d_in[3];
    const float* bk = (const float*)d_in[4];
    const float* Wv = (const float*)d_in[5];
    const float* bv = (const float*)d_in[6];
    const float* Wo = (const float*)d_in[7];
    const float* bo = (const float*)d_in[8];
    float* out = (float*)d_out;

    fused_qkv_attn<<<NHB, 256>>>(x, Wq, bq, Wk, bk, Wv, bv);
    out_proj<<<NHB, 256>>>(x, Wo, bo, out);
}

// round 4
// speedup vs baseline: 5.5360x; 1.1840x over previous
#include <cuda_runtime.h>

#define SQ   1024   // spatial sequence length (16*64)
#define CH   64     // channels == heads (c = 1 per head)
#define BB   2      // batch
#define NHB  128    // b*g head-batches
#define M    16     // Chebyshev nodes / polynomial terms

// Scratch (allocation-free rule: __device__ global)
__device__ float g_o[NHB * SQ];

__device__ __forceinline__ float ex2f(float x) {
    float r;
    asm("ex2.approx.ftz.f32 %0, %1;" : "=f"(r) : "f"(x));
    return r;
}

// ---------------------------------------------------------------------------
// K1: fused per-head QKV projection + rank-1 attention via Chebyshev proxy.
// One block per (batch, head). 512 threads (16 warps for latency hiding).
//   Phase 1: q,k,v rows of the 1x1-conv GEMM (coalesced float2 x reads),
//            q kept in registers.
//   Phase 2: block min/max of q -> interval [c-r, c+r].
//   Phase 3: f(a)=sum exp2(a*kh_t), g(a)=sum v_t*exp2(a*kh_t) at 16
//            Chebyshev nodes (1 node per warp, warp reductions).
//   Phase 4: DCT -> Chebyshev coefficients.
//   Phase 5: Clenshaw per s, o_s = g(q_s)/f(q_s).
// ---------------------------------------------------------------------------
__global__ __launch_bounds__(512) void fused_qkv_attn(
    const float* __restrict__ x,
    const float* __restrict__ Wq, const float* __restrict__ bq,
    const float* __restrict__ Wk, const float* __restrict__ bk,
    const float* __restrict__ Wv, const float* __restrict__ bv)
{
    __shared__ float wq[CH], wk[CH], wv[CH];
    __shared__ float skh[SQ], svv[SQ];
    __shared__ float fj[M], gj[M], ca[M], cb[M];
    __shared__ float rmin[16], rmax[16];
    __shared__ float sc[3];   // center, radius, 1/radius

    const int tid = threadIdx.x;
    const int hb  = blockIdx.x;
    const int b   = hb >> 6;
    const int h   = hb & 63;

    if (tid < CH)            wq[tid]          = Wq[h * CH + tid];
    else if (tid < 2 * CH)   wk[tid - CH]     = Wk[h * CH + (tid - CH)];
    else if (tid < 3 * CH)   wv[tid - 2 * CH] = Wv[h * CH + (tid - 2 * CH)];
    const float bqh = bq[h], bkh = bk[h], bvh = bv[h];
    __syncthreads();

    const float KS = 0.18033688011112042f;   // log2(e) / sqrt(64)
    const int s0 = tid * 2;

    // Phase 1: projections (each thread: 2 consecutive s, coalesced float2)
    float qx = bqh, qy = bqh;
    float kx = bkh, ky = bkh;
    float vx = bvh, vy = bvh;
    const float* xb = x + (size_t)b * CH * SQ + s0;
#pragma unroll
    for (int c = 0; c < CH; c++) {
        float2 xv = *reinterpret_cast<const float2*>(xb + c * SQ);
        float wqc = wq[c], wkc = wk[c], wvc = wv[c];
        qx = fmaf(wqc, xv.x, qx); qy = fmaf(wqc, xv.y, qy);
        kx = fmaf(wkc, xv.x, kx); ky = fmaf(wkc, xv.y, ky);
        vx = fmaf(wvc, xv.x, vx); vy = fmaf(wvc, xv.y, vy);
    }
    float2 khv; khv.x = kx * KS; khv.y = ky * KS;
    *reinterpret_cast<float2*>(skh + s0) = khv;
    float2 vv2; vv2.x = vx; vv2.y = vy;
    *reinterpret_cast<float2*>(svv + s0) = vv2;

    // Phase 2: q min/max (q stays in registers)
    float qmn = fminf(qx, qy);
    float qmx = fmaxf(qx, qy);
#pragma unroll
    for (int d = 16; d; d >>= 1) {
        qmn = fminf(qmn, __shfl_xor_sync(0xffffffffu, qmn, d));
        qmx = fmaxf(qmx, __shfl_xor_sync(0xffffffffu, qmx, d));
    }
    const int w = tid >> 5, l = tid & 31;
    if (l == 0) { rmin[w] = qmn; rmax[w] = qmx; }
    __syncthreads();
    if (tid == 0) {
        float mn = rmin[0], mx = rmax[0];
#pragma unroll
        for (int i = 1; i < 16; i++) { mn = fminf(mn, rmin[i]); mx = fmaxf(mx, rmax[i]); }
        float cc = 0.5f * (mn + mx);
        float rr = fmaxf(0.5f * (mx - mn), 1e-4f);
        sc[0] = cc; sc[1] = rr; sc[2] = 1.0f / rr;
    }
    __syncthreads();
    const float cc = sc[0], rr = sc[1], invr = sc[2];

    // Phase 3: node evaluation — warp w handles node w
    {
        const float PI_M = 3.14159265358979f / (float)M;
        const float xj = cc + rr * cosf(((float)w + 0.5f) * PI_M);
        float f0 = 0.f, g0 = 0.f;
#pragma unroll 8
        for (int t = l; t < SQ; t += 32) {
            float e0 = ex2f(xj * skh[t]);
            f0 += e0;
            g0 = fmaf(e0, svv[t], g0);
        }
#pragma unroll
        for (int d = 16; d; d >>= 1) {
            f0 += __shfl_xor_sync(0xffffffffu, f0, d);
            g0 += __shfl_xor_sync(0xffffffffu, g0, d);
        }
        if (l == 0) { fj[w] = f0; gj[w] = g0; }
    }
    __syncthreads();

    // Phase 4: DCT -> Chebyshev coefficients (threads 0..15)
    if (tid < M) {
        const float PI_M = 3.14159265358979f / (float)M;
        float af = 0.f, ag = 0.f;
#pragma unroll
        for (int j = 0; j < M; j++) {
            float wgt = cosf((float)tid * ((float)j + 0.5f) * PI_M);
            af = fmaf(fj[j], wgt, af);
            ag = fmaf(gj[j], wgt, ag);
        }
        float scale = (tid == 0) ? (1.0f / M) : (2.0f / M);
        ca[tid] = af * scale;
        cb[tid] = ag * scale;
    }
    __syncthreads();

    // Phase 5: Clenshaw evaluation, o_s = g(q_s)/f(q_s) (q from registers)
    float qs[2] = {qx, qy};
    float os[2];
#pragma unroll
    for (int i = 0; i < 2; i++) {
        float u  = (qs[i] - cc) * invr;
        float u2 = 2.f * u;
        float b1 = 0.f, b2 = 0.f, d1 = 0.f, d2 = 0.f;
#pragma unroll
        for (int k = M - 1; k >= 1; k--) {
            float tb = fmaf(u2, b1, ca[k] - b2); b2 = b1; b1 = tb;
            float td = fmaf(u2, d1, cb[k] - d2); d2 = d1; d1 = td;
        }
        float f = fmaf(u, b1, ca[0] - b2);
        float g = fmaf(u, d1, cb[0] - d2);
        os[i] = __fdividef(g, f);
    }
    float2 out2; out2.x = os[0]; out2.y = os[1];
    *reinterpret_cast<float2*>(g_o + hb * SQ + s0) = out2;
}

// ---------------------------------------------------------------------------
// K2: output projection + residual, tiled so every g_o element is read ONCE.
// grid = (SQ/16, BB), block 256.
//   Stage g_o[b, all c, 16-s tile] into smem (one coalesced LDG.128/thread),
//   Wo into padded smem, then each thread computes one (o, 4-s quad).
// ---------------------------------------------------------------------------
__global__ __launch_bounds__(256) void out_proj(
    const float* __restrict__ x,
    const float* __restrict__ Wo, const float* __restrict__ bo,
    float* __restrict__ out)
{
    __shared__ float Wsh[CH][CH + 1];
    __shared__ float tile[CH][16];

    const int tid = threadIdx.x;
    const int bx  = blockIdx.x;        // s-tile index (16 s per tile)
    const int b   = blockIdx.y;
    const int s0  = bx * 16;

    // Stage Wo (4096 floats, 16 per thread, coalesced float4 loads)
#pragma unroll
    for (int i = tid * 4; i < CH * CH; i += 1024) {
        float4 wv = *reinterpret_cast<const float4*>(Wo + i);
        int r = i >> 6, c0 = i & 63;
        Wsh[r][c0 + 0] = wv.x; Wsh[r][c0 + 1] = wv.y;
        Wsh[r][c0 + 2] = wv.z; Wsh[r][c0 + 3] = wv.w;
    }

    // Stage g_o tile: thread (c = tid>>2, j = tid&3) loads one float4
    {
        int c = tid >> 2, j = tid & 3;
        float4 gv = *reinterpret_cast<const float4*>(
            g_o + (size_t)(b * CH + c) * SQ + s0 + j * 4);
        *reinterpret_cast<float4*>(&tile[c][j * 4]) = gv;
    }
    __syncthreads();

    // Compute: thread (o = tid>>2, sq = tid&3) -> out[b, o, s0+sq*4 .. +3]
    const int o  = tid >> 2;
    const int sq = tid & 3;
    const float bias = bo[o];
    float4 acc = {bias, bias, bias, bias};
#pragma unroll
    for (int c = 0; c < CH; c++) {
        float wc = Wsh[o][c];
        float4 gv = *reinterpret_cast<const float4*>(&tile[c][sq * 4]);
        acc.x = fmaf(wc, gv.x, acc.x);
        acc.y = fmaf(wc, gv.y, acc.y);
        acc.z = fmaf(wc, gv.z, acc.z);
        acc.w = fmaf(wc, gv.w, acc.w);
    }
    const size_t idx = (size_t)(b * CH + o) * SQ + s0 + sq * 4;
    const float4 rv = *reinterpret_cast<const float4*>(x + idx);
    acc.x += rv.x; acc.y += rv.y; acc.z += rv.z; acc.w += rv.w;
    *reinterpret_cast<float4*>(out + idx) = acc;
}

extern "C" void kernel_launch(void* const* d_in, const int* in_sizes, int n_in,
                              void* d_out, int out_size)
{
    const float* x  = (const float*)d_in[0];
    const float* Wq = (const float*)d_in[1];
    const float* bq = (const float*)d_in[2];
    const float* Wk = (const float*)d_in[3];
    const float* bk = (const float*)d_in[4];
    const float* Wv = (const float*)d_in[5];
    const float* bv = (const float*)d_in[6];
    const float* Wo = (const float*)d_in[7];
    const float* bo = (const float*)d_in[8];
    float* out = (float*)d_out;

    fused_qkv_attn<<<NHB, 512>>>(x, Wq, bq, Wk, bk, Wv, bv);

    dim3 pgrid(SQ / 16, BB);
    out_proj<<<pgrid, 256>>>(x, Wo, bo, out);
}